// round 3
// baseline (speedup 1.0000x reference)
#include <cuda_runtime.h>
#include <math.h>

#define NN 100000
#define NE 3200000
#define EBLK ((NE + 255) / 256)
#define NBLK ((NN + 255) / 256)
#define SCAN_BLKS 196   // 196*512 = 100352 >= NN

// ---------------- scratch ---------------------------------------------------
__device__ float g_tmpA[NN * 8];
__device__ float g_tmpB[NN * 8];
__device__ int2  g_edge[NE];     // {src, dst}
__device__ int2  g_rec[NE];      // CSR-sorted {src, w_bits}
__device__ int   g_cnt[NN];      // per-dst degree
__device__ int   g_off[NN];      // exclusive offsets
__device__ int   g_pos[NN];      // running scatter cursor
__device__ int   g_bsum[256];
__device__ int   g_bsumx[256];
__device__ int   g_is64;

// ---------------- f32x2 helpers --------------------------------------------
__device__ __forceinline__ unsigned long long bcast2(float x) {
    unsigned long long r;
    unsigned u = __float_as_uint(x);
    asm("mov.b64 %0, {%1, %1};" : "=l"(r) : "r"(u));
    return r;
}
__device__ __forceinline__ void ffma2(unsigned long long& d,
                                      unsigned long long a, unsigned long long b) {
    asm("fma.rn.f32x2 %0, %1, %2, %0;" : "+l"(d) : "l"(a), "l"(b));
}
__device__ __forceinline__ void unpack2(unsigned long long v, float& lo, float& hi) {
    asm("mov.b64 {%0, %1}, %2;" : "=f"(lo), "=f"(hi) : "l"(v));
}

// ---------------- detect int64 vs int32 edge_index -------------------------
__global__ void detect_kernel(const unsigned int* __restrict__ w) {
    unsigned v = w[threadIdx.x * 2 + 1];
    int any = __syncthreads_or(v != 0u);
    if (threadIdx.x == 0) g_is64 = any ? 0 : 1;
}

__global__ void zero_k() {
    int i = blockIdx.x * blockDim.x + threadIdx.x;
    if (i < NN) g_cnt[i] = 0;
}

// convert + histogram of dst
__global__ void hist_convert(const void* __restrict__ edge_index) {
    int e = blockIdx.x * blockDim.x + threadIdx.x;
    if (e >= NE) return;
    int s, d;
    if (g_is64) {
        const long long* p = (const long long*)edge_index;
        s = (int)p[e]; d = (int)p[NE + e];
    } else {
        const int* p = (const int*)edge_index;
        s = p[e]; d = p[NE + e];
    }
    g_edge[e] = make_int2(s, d);
    atomicAdd(&g_cnt[d], 1);
}

// ---------------- 3-kernel exclusive prefix scan ---------------------------
__device__ __forceinline__ int block_incl_scan(int v, int tid) {
    __shared__ int wsum[8];
    int lane = tid & 31, w = tid >> 5;
#pragma unroll
    for (int d = 1; d < 32; d <<= 1) {
        int t = __shfl_up_sync(0xffffffffu, v, d);
        if (lane >= d) v += t;
    }
    if (lane == 31) wsum[w] = v;
    __syncthreads();
    if (w == 0) {
        int s = (lane < 8) ? wsum[lane] : 0;
#pragma unroll
        for (int d = 1; d < 8; d <<= 1) {
            int t = __shfl_up_sync(0xffffffffu, s, d);
            if (lane >= d) s += t;
        }
        if (lane < 8) wsum[lane] = s;
    }
    __syncthreads();
    return v + ((w > 0) ? wsum[w - 1] : 0);
}

__global__ void scanA() {
    int t = threadIdx.x;
    int i0 = blockIdx.x * 512 + 2 * t, i1 = i0 + 1;
    int a = (i0 < NN) ? g_cnt[i0] : 0;
    int b = (i1 < NN) ? g_cnt[i1] : 0;
    int p = a + b;
    int incl = block_incl_scan(p, t);
    int excl = incl - p;
    if (i0 < NN) g_off[i0] = excl;
    if (i1 < NN) g_off[i1] = excl + a;
    if (t == 255) g_bsum[blockIdx.x] = incl;
}

__global__ void scanB() {
    int t = threadIdx.x;
    int v = (t < SCAN_BLKS) ? g_bsum[t] : 0;
    int incl = block_incl_scan(v, t);
    if (t < SCAN_BLKS) g_bsumx[t] = incl - v;
}

__global__ void scanC() {
    int t = threadIdx.x;
    int add = g_bsumx[blockIdx.x];
    int i0 = blockIdx.x * 512 + 2 * t, i1 = i0 + 1;
    if (i0 < NN) { int o = g_off[i0] + add; g_off[i0] = o; g_pos[i0] = o; }
    if (i1 < NN) { int o = g_off[i1] + add; g_off[i1] = o; g_pos[i1] = o; }
}

// scatter edges into CSR order
__global__ void scatter_k(const float* __restrict__ ew) {
    int e = blockIdx.x * blockDim.x + threadIdx.x;
    if (e >= NE) return;
    int2 sd = g_edge[e];
    float w = ew[e];
    int p = atomicAdd(&g_pos[sd.y], 1);
    g_rec[p] = make_int2(sd.x, __float_as_int(w));
}

// ---------------- layer-1: g_tmpA = x @ W1 (512 -> 8) ----------------------
// 8-lane subwarps per node (4 nodes/warp, 32 nodes/block). W1 staged as
// transposed f32-pairs in shared; packed f32x2 FMA; 3-step butterfly reduce.
__global__ void l1_kernel(const float* __restrict__ x, const float* __restrict__ W1) {
    __shared__ float raw[4096];                                  // 16 KB
    __shared__ __align__(16) unsigned long long sh2[2048];       // 16 KB: [p][k]
    const int tid = threadIdx.x;

    // stage W1 coalesced
#pragma unroll
    for (int i = 0; i < 4; i++)
        ((float4*)raw)[tid + i * 256] = __ldg(((const float4*)W1) + tid + i * 256);
    __syncthreads();

    // rearrange: sh2[p*512 + k] = {W1[k][2p], W1[k][2p+1]}
#pragma unroll
    for (int i = tid; i < 2048; i += 256) {
        int idx = ((i & 3) << 9) | (i >> 2);   // bank-friendly remap
        int p = idx >> 9, k = idx & 511;
        unsigned lo = __float_as_uint(raw[k * 8 + 2 * p]);
        unsigned hi = __float_as_uint(raw[k * 8 + 2 * p + 1]);
        unsigned long long v;
        asm("mov.b64 %0, {%1, %2};" : "=l"(v) : "r"(lo), "r"(hi));
        sh2[idx] = v;
    }
    __syncthreads();

    const int lane = tid & 31;
    const int warp = tid >> 5;
    const int g = lane >> 3;       // node within warp (0..3)
    const int r = lane & 7;        // k-sublane (0..7)
    const int node = blockIdx.x * 32 + warp * 4 + g;   // NN = 3125*32 exactly

    const float* xrow = x + (size_t)node * 512;
    unsigned long long acc[4];
#pragma unroll
    for (int p = 0; p < 4; p++) acc[p] = 0ull;

#pragma unroll 4
    for (int i = 0; i < 16; i++) {
        int kbase = i * 32 + r * 4;
        float4 xv = __ldg((const float4*)(xrow + kbase));
        unsigned long long x0 = bcast2(xv.x), x1 = bcast2(xv.y);
        unsigned long long x2 = bcast2(xv.z), x3 = bcast2(xv.w);
#pragma unroll
        for (int p = 0; p < 4; p++) {
            const ulonglong2* wp = (const ulonglong2*)&sh2[p * 512 + kbase];
            ulonglong2 wA = wp[0];
            ulonglong2 wB = wp[1];
            ffma2(acc[p], x0, wA.x);
            ffma2(acc[p], x1, wA.y);
            ffma2(acc[p], x2, wB.x);
            ffma2(acc[p], x3, wB.y);
        }
    }

    // unpack + 8-lane butterfly reduce
    float s[8];
#pragma unroll
    for (int p = 0; p < 4; p++) unpack2(acc[p], s[2 * p], s[2 * p + 1]);
#pragma unroll
    for (int d = 1; d < 8; d <<= 1) {
#pragma unroll
        for (int o = 0; o < 8; o++)
            s[o] += __shfl_xor_sync(0xffffffffu, s[o], d);
    }
    if (r == 0) {
        float4* t = (float4*)(g_tmpA + (size_t)node * 8);
        t[0] = make_float4(s[0], s[1], s[2], s[3]);
        t[1] = make_float4(s[4], s[5], s[6], s[7]);
    }
}

// ---------------- fused gather-aggregate + epilogue ------------------------
// POST: 1 = relu(acc+bias) -> fout ; 2 = relu(acc@W2+b2)@W3 -> fout
//       4 = log_softmax(acc@W4+b4) -> out
template <int POST, bool AB>
__global__ void agg_k(const float* __restrict__ bias,
                      const float* __restrict__ Wa,
                      const float* __restrict__ Wb,
                      float* __restrict__ out) {
    int n = blockIdx.x * blockDim.x + threadIdx.x;
    if (n >= NN) return;
    const float* fin = AB ? g_tmpA : g_tmpB;
    float*      fout = AB ? g_tmpB : g_tmpA;

    int i = g_off[n];
    int end = i + g_cnt[n];
    float4 a0 = make_float4(0.f, 0.f, 0.f, 0.f);
    float4 a1 = a0;

    for (; i + 2 <= end; i += 2) {
        int2 r0 = __ldg(&g_rec[i]);
        int2 r1 = __ldg(&g_rec[i + 1]);
        const float4* p0 = (const float4*)(fin + (size_t)r0.x * 8);
        const float4* p1 = (const float4*)(fin + (size_t)r1.x * 8);
        float4 u0 = __ldg(p0), u1 = __ldg(p0 + 1);
        float4 v0 = __ldg(p1), v1 = __ldg(p1 + 1);
        float w0 = __int_as_float(r0.y), w1 = __int_as_float(r1.y);
        a0.x += w0 * u0.x; a0.y += w0 * u0.y; a0.z += w0 * u0.z; a0.w += w0 * u0.w;
        a1.x += w0 * u1.x; a1.y += w0 * u1.y; a1.z += w0 * u1.z; a1.w += w0 * u1.w;
        a0.x += w1 * v0.x; a0.y += w1 * v0.y; a0.z += w1 * v0.z; a0.w += w1 * v0.w;
        a1.x += w1 * v1.x; a1.y += w1 * v1.y; a1.z += w1 * v1.z; a1.w += w1 * v1.w;
    }
    if (i < end) {
        int2 r0 = __ldg(&g_rec[i]);
        const float4* p0 = (const float4*)(fin + (size_t)r0.x * 8);
        float4 u0 = __ldg(p0), u1 = __ldg(p0 + 1);
        float w0 = __int_as_float(r0.y);
        a0.x += w0 * u0.x; a0.y += w0 * u0.y; a0.z += w0 * u0.z; a0.w += w0 * u0.w;
        a1.x += w0 * u1.x; a1.y += w0 * u1.y; a1.z += w0 * u1.z; a1.w += w0 * u1.w;
    }

    float acc[8] = {a0.x, a0.y, a0.z, a0.w, a1.x, a1.y, a1.z, a1.w};

    if (POST == 1) {
        float4* t = (float4*)(fout + (size_t)n * 8);
        t[0] = make_float4(fmaxf(acc[0] + __ldg(&bias[0]), 0.f),
                           fmaxf(acc[1] + __ldg(&bias[1]), 0.f),
                           fmaxf(acc[2] + __ldg(&bias[2]), 0.f),
                           fmaxf(acc[3] + __ldg(&bias[3]), 0.f));
        t[1] = make_float4(fmaxf(acc[4] + __ldg(&bias[4]), 0.f),
                           fmaxf(acc[5] + __ldg(&bias[5]), 0.f),
                           fmaxf(acc[6] + __ldg(&bias[6]), 0.f),
                           fmaxf(acc[7] + __ldg(&bias[7]), 0.f));
    } else if (POST == 2) {
        // m = relu(acc @ Wa(8x16) + bias), r = m @ Wb(16x8)
        float m[16];
#pragma unroll
        for (int o = 0; o < 16; o++) m[o] = __ldg(&bias[o]);
#pragma unroll
        for (int j = 0; j < 8; j++) {
            float hj = acc[j];
#pragma unroll
            for (int o = 0; o < 16; o++) m[o] += hj * __ldg(&Wa[j * 16 + o]);
        }
#pragma unroll
        for (int o = 0; o < 16; o++) m[o] = fmaxf(m[o], 0.f);
        float rr[8];
#pragma unroll
        for (int o = 0; o < 8; o++) rr[o] = 0.f;
#pragma unroll
        for (int j = 0; j < 16; j++) {
            float mj = m[j];
#pragma unroll
            for (int o = 0; o < 8; o++) rr[o] += mj * __ldg(&Wb[j * 8 + o]);
        }
        float4* t = (float4*)(fout + (size_t)n * 8);
        t[0] = make_float4(rr[0], rr[1], rr[2], rr[3]);
        t[1] = make_float4(rr[4], rr[5], rr[6], rr[7]);
    } else {  // POST == 4
        float v[10];
#pragma unroll
        for (int o = 0; o < 10; o++) v[o] = __ldg(&bias[o]);
#pragma unroll
        for (int j = 0; j < 8; j++) {
            float hj = acc[j];
#pragma unroll
            for (int o = 0; o < 10; o++) v[o] += hj * __ldg(&Wa[j * 10 + o]);
        }
        float mx = -1e30f;
#pragma unroll
        for (int o = 0; o < 10; o++) mx = fmaxf(mx, v[o]);
        float sum = 0.f;
#pragma unroll
        for (int o = 0; o < 10; o++) sum += expf(v[o] - mx);
        float l = logf(sum);
#pragma unroll
        for (int o = 0; o < 10; o++) out[(size_t)n * 10 + o] = v[o] - mx - l;
    }
}

// ---------------- launch ---------------------------------------------------
extern "C" void kernel_launch(void* const* d_in, const int* in_sizes, int n_in,
                              void* d_out, int out_size) {
    const float* x  = (const float*)d_in[0];
    const void*  ei = d_in[1];
    const float* ew = (const float*)d_in[2];
    const float* W1 = (const float*)d_in[3];
    const float* b1 = (const float*)d_in[4];
    const float* W2 = (const float*)d_in[5];
    const float* b2 = (const float*)d_in[6];
    const float* W3 = (const float*)d_in[7];
    const float* b3 = (const float*)d_in[8];
    const float* W4 = (const float*)d_in[9];
    const float* b4 = (const float*)d_in[10];
    float* out = (float*)d_out;

    detect_kernel<<<1, 256>>>((const unsigned int*)ei);
    zero_k<<<NBLK, 256>>>();
    hist_convert<<<EBLK, 256>>>(ei);
    scanA<<<SCAN_BLKS, 256>>>();
    scanB<<<1, 256>>>();
    scanC<<<SCAN_BLKS, 256>>>();
    scatter_k<<<EBLK, 256>>>(ew);

    l1_kernel<<<NN / 32, 256>>>(x, W1);                       // tmpA = x@W1

    agg_k<1, true ><<<NBLK, 256>>>(b1, nullptr, nullptr, nullptr); // B = h1 = relu(A@tmpA + b1)
    agg_k<2, false><<<NBLK, 256>>>(b2, W2, W3, nullptr);           // A = relu((A@h1)W2 + b2)W3
    agg_k<1, true ><<<NBLK, 256>>>(b3, nullptr, nullptr, nullptr); // B = h3 = relu(A@tA + b3)
    agg_k<4, false><<<NBLK, 256>>>(b4, W4, nullptr, out);          // out = lsm((A@h3)W4 + b4)
}